// round 3
// baseline (speedup 1.0000x reference)
#include <cuda_runtime.h>
#include <cstdint>

#define N_NODES 100000
#define NNZ     1600000
#define IN_CH   256
#define OUT_CH  64

// Scratch: projected features Xp [N_NODES, OUT_CH] and transposed weight WT [IN_CH, OUT_CH]
__device__ float g_Xp[(size_t)N_NODES * OUT_CH];   // 25.6 MB
__device__ float g_WT[IN_CH * OUT_CH];             // 64 KB
__device__ int   g_idx_is32;                       // 1 if index arrays are int32, 0 if int64

// ---------------------------------------------------------------------------
// Zero the output buffer (harness poisons it to 0xAA before timing).
// ---------------------------------------------------------------------------
__global__ void zero_out_kernel(float4* __restrict__ out, int n4) {
    int i = blockIdx.x * blockDim.x + threadIdx.x;
    int stride = gridDim.x * blockDim.x;
    for (; i < n4; i += stride)
        out[i] = make_float4(0.f, 0.f, 0.f, 0.f);
}

// ---------------------------------------------------------------------------
// Detect whether L_rows/L_cols are int32 or int64.
// If int64 (values < 2^31, nonnegative), every odd 32-bit word is 0.
// If int32, odd words are random indices in [0, 100000) -> nonzero w.h.p.
// Single block, deterministic.
// ---------------------------------------------------------------------------
__global__ void detect_idx_kernel(const unsigned int* __restrict__ rows_u32) {
    __shared__ int s_any;
    if (threadIdx.x == 0) s_any = 0;
    __syncthreads();
    int local = 0;
    for (int i = threadIdx.x; i < 1024; i += blockDim.x) {
        if (rows_u32[2 * i + 1] != 0u) local = 1;
    }
    if (local) atomicOr(&s_any, 1);
    __syncthreads();
    if (threadIdx.x == 0) g_idx_is32 = s_any;
}

// ---------------------------------------------------------------------------
// Transpose W [OUT_CH, IN_CH] -> WT [IN_CH, OUT_CH] (tiny, one-time per launch)
// ---------------------------------------------------------------------------
__global__ void transpose_w_kernel(const float* __restrict__ W) {
    int idx = blockIdx.x * blockDim.x + threadIdx.x;   // 0 .. 16383
    if (idx < IN_CH * OUT_CH) {
        int o = idx & (OUT_CH - 1);
        int k = idx >> 6;
        g_WT[k * OUT_CH + o] = W[o * IN_CH + k];
    }
}

// ---------------------------------------------------------------------------
// GEMM: Xp = X @ W^T.  CTA = 64 rows x 64 outputs, k-chunked by 64.
// Warp w: output group og = w>>1 (16 outputs), rows = (w&1)*32 + lane.
// Each thread: 16 accumulators.
// Smem: Xs 64x65 (pad -> conflict-free compute loads), Ws 64x64 as float4
// (coalesced STS from pre-transposed WT; broadcast float4 LDS in compute).
// ---------------------------------------------------------------------------
__global__ void __launch_bounds__(256) gemm_kernel(const float* __restrict__ X) {
    __shared__ float  Xs[64 * 65];
    __shared__ float4 Ws[64 * 16];   // [k][o/4]

    const int tid  = threadIdx.x;
    const int warp = tid >> 5;
    const int lane = tid & 31;
    const int og   = warp >> 1;                 // 0..3  -> outputs [og*16, og*16+16)
    const int row_l = ((warp & 1) << 5) + lane; // 0..63
    const int row0 = blockIdx.x * 64;

    float acc[16];
#pragma unroll
    for (int j = 0; j < 16; j++) acc[j] = 0.f;

    for (int kc = 0; kc < IN_CH; kc += 64) {
        // --- load X tile: 64 rows x 64 k, as float4, coalesced ---
#pragma unroll
        for (int i = 0; i < 4; i++) {
            int fidx = tid + i * 256;        // 0..1023 float4 slots
            int r = fidx >> 4;
            int q = fidx & 15;
            int grow = row0 + r;
            if (grow >= N_NODES) grow = N_NODES - 1;   // clamp (harmless dup load)
            float4 v = *reinterpret_cast<const float4*>(X + (size_t)grow * IN_CH + kc + q * 4);
            float* dst = &Xs[r * 65 + q * 4];
            dst[0] = v.x; dst[1] = v.y; dst[2] = v.z; dst[3] = v.w;
        }
        // --- load W tile: 64 k x 64 o from WT, coalesced, conflict-free STS ---
#pragma unroll
        for (int i = 0; i < 4; i++) {
            int fidx = tid + i * 256;
            int kl = fidx >> 4;
            int o4 = fidx & 15;
            Ws[kl * 16 + o4] =
                *reinterpret_cast<const float4*>(g_WT + (kc + kl) * OUT_CH + o4 * 4);
        }
        __syncthreads();

#pragma unroll
        for (int k = 0; k < 64; k++) {
            float xv = Xs[row_l * 65 + k];
            float4 w0 = Ws[k * 16 + og * 4 + 0];
            float4 w1 = Ws[k * 16 + og * 4 + 1];
            float4 w2 = Ws[k * 16 + og * 4 + 2];
            float4 w3 = Ws[k * 16 + og * 4 + 3];
            acc[0]  += xv * w0.x;  acc[1]  += xv * w0.y;
            acc[2]  += xv * w0.z;  acc[3]  += xv * w0.w;
            acc[4]  += xv * w1.x;  acc[5]  += xv * w1.y;
            acc[6]  += xv * w1.z;  acc[7]  += xv * w1.w;
            acc[8]  += xv * w2.x;  acc[9]  += xv * w2.y;
            acc[10] += xv * w2.z;  acc[11] += xv * w2.w;
            acc[12] += xv * w3.x;  acc[13] += xv * w3.y;
            acc[14] += xv * w3.z;  acc[15] += xv * w3.w;
        }
        __syncthreads();
    }

    int grow = row0 + row_l;
    if (grow < N_NODES) {
        float* dst = g_Xp + (size_t)grow * OUT_CH + og * 16;
#pragma unroll
        for (int jj = 0; jj < 4; jj++) {
            reinterpret_cast<float4*>(dst)[jj] =
                make_float4(acc[4 * jj + 0], acc[4 * jj + 1],
                            acc[4 * jj + 2], acc[4 * jj + 3]);
        }
    }
}

// ---------------------------------------------------------------------------
// SpMM scatter: for each edge e, out[rows[e]] += vals[e] * Xp[cols[e]].
// 16 threads per edge, each handles 4 channels (float4 gather + red.v4).
// ---------------------------------------------------------------------------
__global__ void __launch_bounds__(256) spmm_kernel(
    const void* __restrict__ rows_p,
    const void* __restrict__ cols_p,
    const float* __restrict__ vals,
    float* __restrict__ out)
{
    long long gid = (long long)blockIdx.x * 256 + threadIdx.x;
    int e  = (int)(gid >> 4);
    int c4 = (int)(gid & 15);
    if (e >= NNZ) return;

    int row, col;
    if (g_idx_is32) {
        row = __ldg(reinterpret_cast<const int*>(rows_p) + e);
        col = __ldg(reinterpret_cast<const int*>(cols_p) + e);
    } else {
        row = (int)__ldg(reinterpret_cast<const long long*>(rows_p) + e);
        col = (int)__ldg(reinterpret_cast<const long long*>(cols_p) + e);
    }
    float v = __ldg(vals + e);

    float4 x = __ldg(reinterpret_cast<const float4*>(g_Xp) + (size_t)col * 16 + c4);
    float4 r = make_float4(v * x.x, v * x.y, v * x.z, v * x.w);

    float* dst = out + (size_t)row * OUT_CH + c4 * 4;
    asm volatile("red.global.add.v4.f32 [%0], {%1, %2, %3, %4};"
                 :: "l"(dst), "f"(r.x), "f"(r.y), "f"(r.z), "f"(r.w)
                 : "memory");
}

// ---------------------------------------------------------------------------
// kernel_launch
// Inputs (metadata order): g1, g2, X, W_lin, L_rows, L_cols, L_vals
// (robust to the two scalars being dropped: base = n_in - 5)
// ---------------------------------------------------------------------------
extern "C" void kernel_launch(void* const* d_in, const int* in_sizes, int n_in,
                              void* d_out, int out_size) {
    int base = n_in - 5;   // index of X
    const float* X      = reinterpret_cast<const float*>(d_in[base + 0]);
    const float* W      = reinterpret_cast<const float*>(d_in[base + 1]);
    const void*  L_rows = d_in[base + 2];
    const void*  L_cols = d_in[base + 3];
    const float* L_vals = reinterpret_cast<const float*>(d_in[base + 4]);
    float* out = reinterpret_cast<float*>(d_out);

    // 1. zero the output (poisoned by harness)
    int n4 = out_size / 4;   // 6.4M floats -> 1.6M float4
    zero_out_kernel<<<4096, 256>>>(reinterpret_cast<float4*>(out), n4);

    // 2. detect int32 vs int64 index encoding
    detect_idx_kernel<<<1, 256>>>(reinterpret_cast<const unsigned int*>(L_rows));

    // 3. transpose W -> WT
    transpose_w_kernel<<<(IN_CH * OUT_CH + 255) / 256, 256>>>(W);

    // 4. dense projection Xp = X @ W^T
    gemm_kernel<<<(N_NODES + 63) / 64, 256>>>(X);

    // 5. COO SpMM scatter with vectorized global reductions
    long long total = (long long)NNZ * 16;
    int blocks = (int)((total + 255) / 256);
    spmm_kernel<<<blocks, 256>>>(L_rows, L_cols, L_vals, out);
}